// round 4
// baseline (speedup 1.0000x reference)
#include <cuda_runtime.h>
#include <cstdint>
#include <math.h>

// Problem shape (fixed by the reference)
#define NB 32
#define NT 2048
#define ND 128
#define CH 4           // timesteps per chunk (bits per lane nibble)
#define NC 512         // NT / CH

// ---------------------------------------------------------------------------
// Scratch (__device__ globals; no allocations allowed)
// g_mbits: one uint32 per (b, chunk, 8-lane group); bit (4*lane + tt).
// Size = 32*512*16 words = 1MB (L2-resident).
// ---------------------------------------------------------------------------
__device__ int g_is_bool;                           // 1 if mask is 1-byte bools
__device__ unsigned int g_mbits[NB * NC * (ND / 8)];

__global__ void k_init_flag() { g_is_bool = 0; }

// Detect mask storage: int32 0/1 mask -> every 32-bit word is 0 or 1.
// Packed 1-byte bools -> words >1 appear w.p. ~1 over 64K random words.
__global__ void k_detect(const unsigned int* __restrict__ w, int nwords) {
    int i = blockIdx.x * blockDim.x + threadIdx.x;
    if (i < nwords && w[i] > 1u) g_is_bool = 1;
}

// ---------------------------------------------------------------------------
// Pass 1: stream the mask once, pack nibble bitmasks.
// Thread = (b, chunk c, 8-lane group g). Coalesced int4 / uint2 loads.
// ---------------------------------------------------------------------------
__global__ void __launch_bounds__(128) k_mask(const void* __restrict__ mraw) {
    const int gid = blockIdx.x * 128 + threadIdx.x;
    const int g = gid & 15;                  // ND/8 = 16 lane groups
    const int c = (gid >> 4) & (NC - 1);
    const int b = gid >> 13;                 // 4 + log2(NC)

    unsigned int bits = 0;

    if (g_is_bool != 0) {
        // 8 bool bytes per lane group -> one uint2 per timestep
        const uint2* m = (const uint2*)mraw;
        const int base = (b * NT + c * CH) * (ND / 8) + g;
#pragma unroll
        for (int tt = 0; tt < CH; ++tt) {
            uint2 w = m[base + tt * (ND / 8)];
#pragma unroll
            for (int l = 0; l < 4; ++l) {
                bits |= (((w.x >> (8 * l)) & 0xffu) ? 1u : 0u) << (4 * l + tt);
                bits |= (((w.y >> (8 * l)) & 0xffu) ? 1u : 0u) << (4 * (l + 4) + tt);
            }
        }
    } else {
        // 8 int32 per lane group -> two int4 per timestep
        const int4* m = (const int4*)mraw;
        const int base = (b * NT + c * CH) * (ND / 4) + g * 2;
#pragma unroll
        for (int tt = 0; tt < CH; ++tt) {
            int4 w0 = m[base + tt * (ND / 4)];
            int4 w1 = m[base + tt * (ND / 4) + 1];
            bits |= (w0.x ? 1u : 0u) << (0  + tt);
            bits |= (w0.y ? 1u : 0u) << (4  + tt);
            bits |= (w0.z ? 1u : 0u) << (8  + tt);
            bits |= (w0.w ? 1u : 0u) << (12 + tt);
            bits |= (w1.x ? 1u : 0u) << (16 + tt);
            bits |= (w1.y ? 1u : 0u) << (20 + tt);
            bits |= (w1.z ? 1u : 0u) << (24 + tt);
            bits |= (w1.w ? 1u : 0u) << (28 + tt);
        }
    }
    g_mbits[(b * NC + c) * (ND / 8) + g] = bits;
}

// ---------------------------------------------------------------------------
// Pass 2: interpolation. Thread = (b, chunk c, 2-lane pair). All state in
// registers; bulk loads issued before the dependent seed chain.
// ---------------------------------------------------------------------------
__global__ void __launch_bounds__(128) k_interp(const float* __restrict__ v,
                                                const float* __restrict__ t,
                                                float* __restrict__ out) {
    const int gid = blockIdx.x * 128 + threadIdx.x;
    const int dg = gid & 63;                 // ND/2 = 64 lane pairs
    const int c  = (gid >> 6) & (NC - 1);
    const int b  = gid >> 15;                // 6 + log2(NC)
    const int d2 = dg * 2;
    const int s0 = 4 * (d2 & 7);             // nibble shift, lane 0
    const int s1 = s0 + 4;                   // nibble shift, lane 1

    const float2* v2 = (const float2*)v;
    const float2* t2 = (const float2*)t;
    float2* o2 = (float2*)out;
    const int base2 = (b * NT + c * CH) * (ND / 2) + dg;
    const int rb = b * NT * ND + d2;         // scalar row base (lane 0)

    // ---- bulk chunk loads first (front-batched, overlap seed chain) ----
    float2 VV[CH], TVa[CH];
#pragma unroll
    for (int tt = 0; tt < CH; ++tt) {
        VV[tt]  = v2[base2 + tt * (ND / 2)];
        TVa[tt] = t2[base2 + tt * (ND / 2)];
    }

    const unsigned int* mrow = &g_mbits[b * NC * (ND / 8) + (d2 >> 3)];
    const unsigned int mw = mrow[c * (ND / 8)];
    const unsigned int nibA = (mw >> s0) & 0xFu;
    const unsigned int nibB = (mw >> s1) & 0xFu;

    // ---- backward seeds: first observation in any later chunk ----
    float nx0 = 0.f, nx1 = 0.f, nt0, nt1;
    bool nv0 = false, nv1 = false;
    for (int j = c + 1; j < NC; ++j) {
        unsigned int w = mrow[j * (ND / 8)];
        unsigned int n0 = (w >> s0) & 0xFu;
        unsigned int n1 = (w >> s1) & 0xFu;
        if (!nv0 && n0) { int gi = rb + (j * CH + __ffs(n0) - 1) * ND;
                          nx0 = v[gi]; nt0 = t[gi]; nv0 = true; }
        if (!nv1 && n1) { int gi = rb + 1 + (j * CH + __ffs(n1) - 1) * ND;
                          nx1 = v[gi]; nt1 = t[gi]; nv1 = true; }
        if (nv0 && nv1) break;
    }
    if (!nv0) nt0 = t[rb + (NT - 1) * ND];        // tmax (times are cumsum)
    if (!nv1) nt1 = t[rb + 1 + (NT - 1) * ND];

    // ---- forward seeds: last observation in any earlier chunk ----
    float lx0 = 0.f, lx1 = 0.f, lt0, lt1;
    bool lv0 = false, lv1 = false;
    for (int j = c - 1; j >= 0; --j) {
        unsigned int w = mrow[j * (ND / 8)];
        unsigned int n0 = (w >> s0) & 0xFu;
        unsigned int n1 = (w >> s1) & 0xFu;
        if (!lv0 && n0) { int gi = rb + (j * CH + 31 - __clz(n0)) * ND;
                          lx0 = v[gi]; lt0 = t[gi]; lv0 = true; }
        if (!lv1 && n1) { int gi = rb + 1 + (j * CH + 31 - __clz(n1)) * ND;
                          lx1 = v[gi]; lt1 = t[gi]; lv1 = true; }
        if (lv0 && lv1) break;
    }
    if (!lv0) lt0 = t[rb];                        // t0 = times[b, 0, d]
    if (!lv1) lt1 = t[rb + 1];

    // ---- backward inclusive fill (registers) ----
    float2 NNX[CH], NNT[CH];
#pragma unroll
    for (int tt = CH - 1; tt >= 0; --tt) {
        if ((nibA >> tt) & 1u) { nx0 = VV[tt].x; nt0 = TVa[tt].x; }
        if ((nibB >> tt) & 1u) { nx1 = VV[tt].y; nt1 = TVa[tt].y; }
        NNX[tt] = make_float2(nx0, nx1);
        NNT[tt] = make_float2(nt0, nt1);
    }

    // ---- forward sweep: inclusive forward fill + interpolation ----
#pragma unroll
    for (int tt = 0; tt < CH; ++tt) {
        float2 o;
        if ((nibA >> tt) & 1u) {
            lx0 = VV[tt].x; lt0 = TVa[tt].x;
            o.x = VV[tt].x;
        } else {
            float den = NNT[tt].x - lt0;
            float num = lx0 * (NNT[tt].x - TVa[tt].x) + NNX[tt].x * (TVa[tt].x - lt0);
            float r = __fdividef(num, den);
            o.x = (den != 0.f && isfinite(r)) ? r : 0.f;
        }
        if ((nibB >> tt) & 1u) {
            lx1 = VV[tt].y; lt1 = TVa[tt].y;
            o.y = VV[tt].y;
        } else {
            float den = NNT[tt].y - lt1;
            float num = lx1 * (NNT[tt].y - TVa[tt].y) + NNX[tt].y * (TVa[tt].y - lt1);
            float r = __fdividef(num, den);
            o.y = (den != 0.f && isfinite(r)) ? r : 0.f;
        }
        o2[base2 + tt * (ND / 2)] = o;
    }
}

// ---------------------------------------------------------------------------
extern "C" void kernel_launch(void* const* d_in, const int* in_sizes, int n_in,
                              void* d_out, int out_size) {
    const float* values = (const float*)d_in[0];
    const float* times  = (const float*)d_in[1];
    const void*  mask   = d_in[2];

    (void)n_in; (void)in_sizes; (void)out_size;

    // Mask dtype detection (deterministic; same result every replay)
    k_init_flag<<<1, 1>>>();
    const int nwords = 65536;                // 256KB scan, safe for both layouts
    k_detect<<<nwords / 256, 256>>>((const unsigned int*)mask, nwords);

    // Pass 1: pack nibble bitmasks (streams mask exactly once, writes 1MB)
    k_mask<<<(NB * NC * (ND / 8)) / 128, 128>>>(mask);

    // Pass 2: interpolation (streams v, t once; writes out once)
    k_interp<<<(NB * NC * (ND / 2)) / 128, 128>>>(values, times, (float*)d_out);
}

// round 5
// speedup vs baseline: 1.0571x; 1.0571x over previous
#include <cuda_runtime.h>
#include <cstdint>
#include <math.h>

// Problem shape (fixed by the reference)
#define NB 32
#define NT 2048
#define ND 128
#define CH 8           // timesteps per chunk (bits per lane byte)
#define NC 256         // NT / CH

// ---------------------------------------------------------------------------
// Scratch (__device__ globals; no allocations allowed)
// g_mbits: one uint32 per (b, chunk, 4-lane group); bit (8*lane_in_group + tt).
// Size = 32*256*32 words = 1MB (L2-resident, hot).
// ---------------------------------------------------------------------------
__device__ int g_is_bool = 0;                     // 1 if mask is 1-byte bools
__device__ unsigned int g_mbits[NB * NC * (ND / 4)];

// Detect mask storage: int32 0/1 mask -> every 32-bit word is 0 or 1.
// Packed 1-byte bools -> words >1 appear w.p. ~1 over 64K random words.
// Monotone-idempotent across graph replays for a fixed input (only ORs in 1),
// so no reset kernel is needed.
__global__ void k_detect(const unsigned int* __restrict__ w, int nwords) {
    int i = blockIdx.x * blockDim.x + threadIdx.x;
    if (i < nwords && w[i] > 1u) g_is_bool = 1;
}

// ---------------------------------------------------------------------------
// Pass 1: stream the mask once, pack byte bitmasks.
// Thread = (b, chunk c, 4-lane group g). Coalesced word / int4 loads.
// ---------------------------------------------------------------------------
__global__ void __launch_bounds__(128) k_mask(const void* __restrict__ mraw) {
    const int gid = blockIdx.x * 128 + threadIdx.x;
    const int g = gid & 31;                  // ND/4 = 32 lane groups
    const int c = (gid >> 5) & (NC - 1);
    const int b = gid >> 13;                 // 5 + log2(NC)

    unsigned int bits = 0;

    if (g_is_bool != 0) {
        // 4 bool bytes per lane group -> one uint32 per timestep
        const unsigned int* m = (const unsigned int*)mraw;
        const int base = (b * NT + c * CH) * (ND / 4) + g;
#pragma unroll
        for (int tt = 0; tt < CH; ++tt) {
            unsigned int w = m[base + tt * (ND / 4)];
            bits |= ((w         & 0xffu) ? 1u : 0u) << (0  + tt);
            bits |= (((w >> 8)  & 0xffu) ? 1u : 0u) << (8  + tt);
            bits |= (((w >> 16) & 0xffu) ? 1u : 0u) << (16 + tt);
            bits |= (((w >> 24)        ) ? 1u : 0u) << (24 + tt);
        }
    } else {
        // 4 int32 per lane group -> one int4 per timestep
        const int4* m = (const int4*)mraw;
        const int base = (b * NT + c * CH) * (ND / 4) + g;
#pragma unroll
        for (int tt = 0; tt < CH; ++tt) {
            int4 w = m[base + tt * (ND / 4)];
            bits |= (w.x ? 1u : 0u) << (0  + tt);
            bits |= (w.y ? 1u : 0u) << (8  + tt);
            bits |= (w.z ? 1u : 0u) << (16 + tt);
            bits |= (w.w ? 1u : 0u) << (24 + tt);
        }
    }
    g_mbits[(b * NC + c) * (ND / 4) + g] = bits;
}

// ---------------------------------------------------------------------------
// Pass 2: interpolation. Thread = (b, chunk c, 2-lane pair). All state in
// registers. Forward sweep first (fills LX/LT/TV); backward sweep computes
// output directly (at observed positions forward fill == v, so no VV array).
// ---------------------------------------------------------------------------
__global__ void __launch_bounds__(128, 8) k_interp(const float* __restrict__ v,
                                                   const float* __restrict__ t,
                                                   float* __restrict__ out) {
    const int gid = blockIdx.x * 128 + threadIdx.x;
    const int dg = gid & 63;                 // ND/2 = 64 lane pairs
    const int c  = (gid >> 6) & (NC - 1);
    const int b  = gid >> 14;                // 6 + log2(NC)
    const int d2 = dg * 2;
    const int s0 = 8 * (d2 & 3);             // byte shift, lane 0
    const int s1 = s0 + 8;                   // byte shift, lane 1

    const float2* v2 = (const float2*)v;
    const float2* t2 = (const float2*)t;
    float2* o2 = (float2*)out;
    const int base2 = (b * NT + c * CH) * (ND / 2) + dg;
    const int rb = b * NT * ND + d2;         // scalar row base (lane 0)

    const unsigned int* mrow = &g_mbits[b * NC * (ND / 4) + (d2 >> 2)];
    const unsigned int mw = mrow[c * (ND / 4)];
    const unsigned int bA = (mw >> s0) & 0xffu;
    const unsigned int bB = (mw >> s1) & 0xffu;

    // ---- forward seeds: last observation in any earlier chunk ----
    float lx0 = 0.f, lx1 = 0.f, lt0, lt1;
    bool lv0 = false, lv1 = false;
    for (int j = c - 1; j >= 0; --j) {
        unsigned int w = mrow[j * (ND / 4)];
        unsigned int n0 = (w >> s0) & 0xffu;
        unsigned int n1 = (w >> s1) & 0xffu;
        if (!lv0 && n0) { int gi = rb + (j * CH + 31 - __clz(n0)) * ND;
                          lx0 = v[gi]; lt0 = t[gi]; lv0 = true; }
        if (!lv1 && n1) { int gi = rb + 1 + (j * CH + 31 - __clz(n1)) * ND;
                          lx1 = v[gi]; lt1 = t[gi]; lv1 = true; }
        if (lv0 && lv1) break;
    }
    if (!lv0) lt0 = t[rb];                        // t0 = times[b, 0, d]
    if (!lv1) lt1 = t[rb + 1];

    // ---- forward sweep: inclusive forward fill into registers ----
    float2 TV[CH], LX[CH], LT[CH];
#pragma unroll
    for (int tt = 0; tt < CH; ++tt) {
        float2 vv = v2[base2 + tt * (ND / 2)];
        float2 tv = t2[base2 + tt * (ND / 2)];
        TV[tt] = tv;
        if ((bA >> tt) & 1u) { lx0 = vv.x; lt0 = tv.x; }
        if ((bB >> tt) & 1u) { lx1 = vv.y; lt1 = tv.y; }
        LX[tt] = make_float2(lx0, lx1);
        LT[tt] = make_float2(lt0, lt1);
    }

    // ---- backward seeds: first observation in any later chunk ----
    float nx0 = 0.f, nx1 = 0.f, nt0, nt1;
    bool nv0 = false, nv1 = false;
    for (int j = c + 1; j < NC; ++j) {
        unsigned int w = mrow[j * (ND / 4)];
        unsigned int n0 = (w >> s0) & 0xffu;
        unsigned int n1 = (w >> s1) & 0xffu;
        if (!nv0 && n0) { int gi = rb + (j * CH + __ffs(n0) - 1) * ND;
                          nx0 = v[gi]; nt0 = t[gi]; nv0 = true; }
        if (!nv1 && n1) { int gi = rb + 1 + (j * CH + __ffs(n1) - 1) * ND;
                          nx1 = v[gi]; nt1 = t[gi]; nv1 = true; }
        if (nv0 && nv1) break;
    }
    if (!nv0) nt0 = t[rb + (NT - 1) * ND];        // tmax (times are cumsum)
    if (!nv1) nt1 = t[rb + 1 + (NT - 1) * ND];

    // ---- backward sweep: inclusive backward fill + interpolation ----
#pragma unroll
    for (int tt = CH - 1; tt >= 0; --tt) {
        float2 o;
        // lane 0
        if ((bA >> tt) & 1u) {
            nx0 = LX[tt].x; nt0 = TV[tt].x;       // observed: LX == v here
            o.x = nx0;
        } else {
            float den = nt0 - LT[tt].x;
            float num = LX[tt].x * (nt0 - TV[tt].x) + nx0 * (TV[tt].x - LT[tt].x);
            float r = __fdividef(num, den);
            o.x = (den != 0.f && isfinite(r)) ? r : 0.f;
        }
        // lane 1
        if ((bB >> tt) & 1u) {
            nx1 = LX[tt].y; nt1 = TV[tt].y;
            o.y = nx1;
        } else {
            float den = nt1 - LT[tt].y;
            float num = LX[tt].y * (nt1 - TV[tt].y) + nx1 * (TV[tt].y - LT[tt].y);
            float r = __fdividef(num, den);
            o.y = (den != 0.f && isfinite(r)) ? r : 0.f;
        }
        o2[base2 + tt * (ND / 2)] = o;
    }
}

// ---------------------------------------------------------------------------
extern "C" void kernel_launch(void* const* d_in, const int* in_sizes, int n_in,
                              void* d_out, int out_size) {
    const float* values = (const float*)d_in[0];
    const float* times  = (const float*)d_in[1];
    const void*  mask   = d_in[2];

    (void)n_in; (void)in_sizes; (void)out_size;

    // Mask dtype detection (idempotent; same result every replay)
    const int nwords = 65536;                // 256KB scan, safe for both layouts
    k_detect<<<nwords / 256, 256>>>((const unsigned int*)mask, nwords);

    // Pass 1: pack byte bitmasks (streams mask exactly once, writes 1MB)
    k_mask<<<(NB * NC * (ND / 4)) / 128, 128>>>(mask);

    // Pass 2: interpolation (streams v, t once; writes out once)
    k_interp<<<(NB * NC * (ND / 2)) / 128, 128>>>(values, times, (float*)d_out);
}

// round 6
// speedup vs baseline: 1.0989x; 1.0396x over previous
#include <cuda_runtime.h>
#include <cstdint>
#include <math.h>

// Problem shape (fixed by the reference)
#define NB 32
#define NT 2048
#define ND 128
#define CH 8           // timesteps per chunk (bits per lane byte)
#define NC 256         // NT / CH

// ---------------------------------------------------------------------------
// Scratch (__device__ globals; no allocations allowed)
// g_mbits: one uint32 per (b, chunk, 4-lane group); bit (8*lane_in_group + tt).
// Size = 32*256*32 words = 1MB (L2-resident, hot).
// ---------------------------------------------------------------------------
__device__ unsigned int g_mbits[NB * NC * (ND / 4)];

// ---------------------------------------------------------------------------
// Pass 1: stream the mask once, pack byte bitmasks.
// Block-local mask-dtype detection: first warp reads words 0..31 of the mask
// buffer (one hot 128B line). int32 0/1 mask -> all words are 0/1 -> isb=0.
// Packed 1-byte bools -> P(all 32 words <= 1) = (1/8)^32 ~ 2^-96 -> isb=1.
// Deterministic for a fixed input; identical across blocks and replays.
// Thread = (b, chunk c, 4-lane group g). Coalesced word / int4 loads.
// ---------------------------------------------------------------------------
__global__ void __launch_bounds__(256) k_mask(const void* __restrict__ mraw) {
    __shared__ int s_isb;
    if (threadIdx.x < 32) {
        unsigned int w = ((const unsigned int*)mraw)[threadIdx.x];
        unsigned int any = __ballot_sync(0xffffffffu, w > 1u);
        if (threadIdx.x == 0) s_isb = (any != 0u);
    }
    __syncthreads();
    const bool isb = (s_isb != 0);

    const int gid = blockIdx.x * 256 + threadIdx.x;
    const int g = gid & 31;                  // ND/4 = 32 lane groups
    const int c = (gid >> 5) & (NC - 1);
    const int b = gid >> 13;                 // 5 + log2(NC)

    unsigned int bits = 0;

    if (isb) {
        // 4 bool bytes per lane group -> one uint32 per timestep
        const unsigned int* m = (const unsigned int*)mraw;
        const int base = (b * NT + c * CH) * (ND / 4) + g;
#pragma unroll
        for (int tt = 0; tt < CH; ++tt) {
            unsigned int w = m[base + tt * (ND / 4)];
            bits |= ((w         & 0xffu) ? 1u : 0u) << (0  + tt);
            bits |= (((w >> 8)  & 0xffu) ? 1u : 0u) << (8  + tt);
            bits |= (((w >> 16) & 0xffu) ? 1u : 0u) << (16 + tt);
            bits |= (((w >> 24)        ) ? 1u : 0u) << (24 + tt);
        }
    } else {
        // 4 int32 per lane group -> one int4 per timestep
        const int4* m = (const int4*)mraw;
        const int base = (b * NT + c * CH) * (ND / 4) + g;
#pragma unroll
        for (int tt = 0; tt < CH; ++tt) {
            int4 w = m[base + tt * (ND / 4)];
            bits |= (w.x ? 1u : 0u) << (0  + tt);
            bits |= (w.y ? 1u : 0u) << (8  + tt);
            bits |= (w.z ? 1u : 0u) << (16 + tt);
            bits |= (w.w ? 1u : 0u) << (24 + tt);
        }
    }
    g_mbits[(b * NC + c) * (ND / 4) + g] = bits;
}

// ---------------------------------------------------------------------------
// Pass 2: interpolation. Thread = (b, chunk c, 2-lane pair). All state in
// registers. Forward sweep first (fills LX/LT/TV); backward sweep computes
// output directly (at observed positions forward fill == v, so no VV array).
// ---------------------------------------------------------------------------
__global__ void __launch_bounds__(128, 8) k_interp(const float* __restrict__ v,
                                                   const float* __restrict__ t,
                                                   float* __restrict__ out) {
    const int gid = blockIdx.x * 128 + threadIdx.x;
    const int dg = gid & 63;                 // ND/2 = 64 lane pairs
    const int c  = (gid >> 6) & (NC - 1);
    const int b  = gid >> 14;                // 6 + log2(NC)
    const int d2 = dg * 2;
    const int s0 = 8 * (d2 & 3);             // byte shift, lane 0
    const int s1 = s0 + 8;                   // byte shift, lane 1

    const float2* v2 = (const float2*)v;
    const float2* t2 = (const float2*)t;
    float2* o2 = (float2*)out;
    const int base2 = (b * NT + c * CH) * (ND / 2) + dg;
    const int rb = b * NT * ND + d2;         // scalar row base (lane 0)

    const unsigned int* mrow = &g_mbits[b * NC * (ND / 4) + (d2 >> 2)];
    const unsigned int mw = mrow[c * (ND / 4)];
    const unsigned int bA = (mw >> s0) & 0xffu;
    const unsigned int bB = (mw >> s1) & 0xffu;

    // ---- forward seeds: last observation in any earlier chunk ----
    float lx0 = 0.f, lx1 = 0.f, lt0, lt1;
    bool lv0 = false, lv1 = false;
    for (int j = c - 1; j >= 0; --j) {
        unsigned int w = mrow[j * (ND / 4)];
        unsigned int n0 = (w >> s0) & 0xffu;
        unsigned int n1 = (w >> s1) & 0xffu;
        if (!lv0 && n0) { int gi = rb + (j * CH + 31 - __clz(n0)) * ND;
                          lx0 = v[gi]; lt0 = t[gi]; lv0 = true; }
        if (!lv1 && n1) { int gi = rb + 1 + (j * CH + 31 - __clz(n1)) * ND;
                          lx1 = v[gi]; lt1 = t[gi]; lv1 = true; }
        if (lv0 && lv1) break;
    }
    if (!lv0) lt0 = t[rb];                        // t0 = times[b, 0, d]
    if (!lv1) lt1 = t[rb + 1];

    // ---- forward sweep: inclusive forward fill into registers ----
    float2 TV[CH], LX[CH], LT[CH];
#pragma unroll
    for (int tt = 0; tt < CH; ++tt) {
        float2 vv = v2[base2 + tt * (ND / 2)];
        float2 tv = t2[base2 + tt * (ND / 2)];
        TV[tt] = tv;
        if ((bA >> tt) & 1u) { lx0 = vv.x; lt0 = tv.x; }
        if ((bB >> tt) & 1u) { lx1 = vv.y; lt1 = tv.y; }
        LX[tt] = make_float2(lx0, lx1);
        LT[tt] = make_float2(lt0, lt1);
    }

    // ---- backward seeds: first observation in any later chunk ----
    float nx0 = 0.f, nx1 = 0.f, nt0, nt1;
    bool nv0 = false, nv1 = false;
    for (int j = c + 1; j < NC; ++j) {
        unsigned int w = mrow[j * (ND / 4)];
        unsigned int n0 = (w >> s0) & 0xffu;
        unsigned int n1 = (w >> s1) & 0xffu;
        if (!nv0 && n0) { int gi = rb + (j * CH + __ffs(n0) - 1) * ND;
                          nx0 = v[gi]; nt0 = t[gi]; nv0 = true; }
        if (!nv1 && n1) { int gi = rb + 1 + (j * CH + __ffs(n1) - 1) * ND;
                          nx1 = v[gi]; nt1 = t[gi]; nv1 = true; }
        if (nv0 && nv1) break;
    }
    if (!nv0) nt0 = t[rb + (NT - 1) * ND];        // tmax (times are cumsum)
    if (!nv1) nt1 = t[rb + 1 + (NT - 1) * ND];

    // ---- backward sweep: inclusive backward fill + interpolation ----
#pragma unroll
    for (int tt = CH - 1; tt >= 0; --tt) {
        float2 o;
        // lane 0
        if ((bA >> tt) & 1u) {
            nx0 = LX[tt].x; nt0 = TV[tt].x;       // observed: LX == v here
            o.x = nx0;
        } else {
            float den = nt0 - LT[tt].x;
            float num = LX[tt].x * (nt0 - TV[tt].x) + nx0 * (TV[tt].x - LT[tt].x);
            float r = __fdividef(num, den);
            o.x = (den != 0.f && isfinite(r)) ? r : 0.f;
        }
        // lane 1
        if ((bB >> tt) & 1u) {
            nx1 = LX[tt].y; nt1 = TV[tt].y;
            o.y = nx1;
        } else {
            float den = nt1 - LT[tt].y;
            float num = LX[tt].y * (nt1 - TV[tt].y) + nx1 * (TV[tt].y - LT[tt].y);
            float r = __fdividef(num, den);
            o.y = (den != 0.f && isfinite(r)) ? r : 0.f;
        }
        o2[base2 + tt * (ND / 2)] = o;
    }
}

// ---------------------------------------------------------------------------
extern "C" void kernel_launch(void* const* d_in, const int* in_sizes, int n_in,
                              void* d_out, int out_size) {
    const float* values = (const float*)d_in[0];
    const float* times  = (const float*)d_in[1];
    const void*  mask   = d_in[2];

    (void)n_in; (void)in_sizes; (void)out_size;

    // Pass 1: pack byte bitmasks (streams mask exactly once; detection is
    // block-local inside the kernel — no separate detect launch)
    k_mask<<<(NB * NC * (ND / 4)) / 256, 256>>>(mask);

    // Pass 2: interpolation (streams v, t once; writes out once)
    k_interp<<<(NB * NC * (ND / 2)) / 128, 128>>>(values, times, (float*)d_out);
}

// round 7
// speedup vs baseline: 1.1671x; 1.0621x over previous
#include <cuda_runtime.h>
#include <cstdint>
#include <math.h>

// Problem shape (fixed by the reference)
#define NB 32
#define NT 2048
#define ND 128
#define CH 8           // timesteps per thread-chunk
#define NC 256         // NT / CH

// ---------------------------------------------------------------------------
// Single fused kernel. Thread = (b, chunk c, lane pair d2=2*dg).
// - Block-local mask dtype detection (ballot over first 32 words).
// - Chunk mask bits read inline with the v/t stream.
// - Seed search probes the raw mask in batches of 4 independent loads
//   (expected ~1.1 batches per direction at p(observed)=1/2).
// - Forward sweep fills LX/LT/TV registers; backward sweep interpolates.
// ---------------------------------------------------------------------------
__global__ void __launch_bounds__(128) k_all(const float* __restrict__ v,
                                             const float* __restrict__ t,
                                             const void*  __restrict__ mraw,
                                             float* __restrict__ out) {
    // ---- mask dtype detection: int32 0/1 words are always <=1; packed bool
    // bytes give a word >1 over 32 words w.p. 1 - (1/8)^32. If bools happen to
    // be stored as int32 0/1 we take the int path, which is also correct.
    __shared__ int s_isb;
    if (threadIdx.x < 32) {
        unsigned int w = ((const unsigned int*)mraw)[threadIdx.x];
        unsigned int any = __ballot_sync(0xffffffffu, w > 1u);
        if (threadIdx.x == 0) s_isb = (any != 0u);
    }
    __syncthreads();
    const bool isb = (s_isb != 0);

    const int gid = blockIdx.x * 128 + threadIdx.x;
    const int dg = gid & 63;                 // ND/2 = 64 lane pairs
    const int c  = (gid >> 6) & (NC - 1);
    const int b  = gid >> 14;                // 6 + log2(NC)
    const int d2 = dg * 2;

    const float2* v2 = (const float2*)v;
    const float2* t2 = (const float2*)t;
    float2* o2 = (float2*)out;

    const int rb  = b * NT * ND + d2;            // scalar row base (lane 0)
    const int rb2 = b * NT * (ND / 2) + dg;      // float2/int2 row base
    const int base2 = rb2 + (c * CH) * (ND / 2);
    const unsigned char* m8 = (const unsigned char*)mraw;
    const int2* m32 = (const int2*)mraw;

    // ---- chunk mask bits (tiny loads; warp-coalesced) ----
    unsigned int bA = 0, bB = 0;
    if (isb) {
#pragma unroll
        for (int tt = 0; tt < CH; ++tt) {
            unsigned short w = *(const unsigned short*)(m8 + rb + (c * CH + tt) * ND);
            bA |= ((w & 0xffu) ? 1u : 0u) << tt;
            bB |= ((w >> 8)    ? 1u : 0u) << tt;
        }
    } else {
#pragma unroll
        for (int tt = 0; tt < CH; ++tt) {
            int2 w = m32[base2 + tt * (ND / 2)];
            bA |= (w.x ? 1u : 0u) << tt;
            bB |= (w.y ? 1u : 0u) << tt;
        }
    }

    // ---- forward seed: last observation before this chunk ----
    // Region [0, c*CH) has length multiple of 8 -> batches of 4 never cross 0.
    int f0 = -1, f1 = -1;
    {
        int ti = c * CH - 1;
        if (isb) {
            while ((f0 < 0 || f1 < 0) && ti >= 0) {
                unsigned short w0 = *(const unsigned short*)(m8 + rb + (ti    ) * ND);
                unsigned short w1 = *(const unsigned short*)(m8 + rb + (ti - 1) * ND);
                unsigned short w2 = *(const unsigned short*)(m8 + rb + (ti - 2) * ND);
                unsigned short w3 = *(const unsigned short*)(m8 + rb + (ti - 3) * ND);
                if (f0 < 0) f0 = (w0 & 0xffu) ? ti : (w1 & 0xffu) ? ti-1 : (w2 & 0xffu) ? ti-2 : (w3 & 0xffu) ? ti-3 : -1;
                if (f1 < 0) f1 = (w0 >> 8) ? ti : (w1 >> 8) ? ti-1 : (w2 >> 8) ? ti-2 : (w3 >> 8) ? ti-3 : -1;
                ti -= 4;
            }
        } else {
            while ((f0 < 0 || f1 < 0) && ti >= 0) {
                int2 w0 = m32[rb2 + (ti    ) * (ND / 2)];
                int2 w1 = m32[rb2 + (ti - 1) * (ND / 2)];
                int2 w2 = m32[rb2 + (ti - 2) * (ND / 2)];
                int2 w3 = m32[rb2 + (ti - 3) * (ND / 2)];
                if (f0 < 0) f0 = w0.x ? ti : w1.x ? ti-1 : w2.x ? ti-2 : w3.x ? ti-3 : -1;
                if (f1 < 0) f1 = w0.y ? ti : w1.y ? ti-1 : w2.y ? ti-2 : w3.y ? ti-3 : -1;
                ti -= 4;
            }
        }
    }
    float lx0 = 0.f, lx1 = 0.f, lt0, lt1;
    if (f0 >= 0) { lx0 = v[rb + f0 * ND];     lt0 = t[rb + f0 * ND];     } else lt0 = t[rb];
    if (f1 >= 0) { lx1 = v[rb + 1 + f1 * ND]; lt1 = t[rb + 1 + f1 * ND]; } else lt1 = t[rb + 1];

    // ---- forward sweep: inclusive forward fill into registers ----
    float2 TV[CH], LX[CH], LT[CH];
#pragma unroll
    for (int tt = 0; tt < CH; ++tt) {
        float2 vv = v2[base2 + tt * (ND / 2)];
        float2 tv = t2[base2 + tt * (ND / 2)];
        TV[tt] = tv;
        if ((bA >> tt) & 1u) { lx0 = vv.x; lt0 = tv.x; }
        if ((bB >> tt) & 1u) { lx1 = vv.y; lt1 = tv.y; }
        LX[tt] = make_float2(lx0, lx1);
        LT[tt] = make_float2(lt0, lt1);
    }

    // ---- backward seed: first observation after this chunk ----
    // Region [(c+1)*CH, NT) has length multiple of 8 -> batches stay in range.
    int n0i = -1, n1i = -1;
    {
        int ti = (c + 1) * CH;
        if (isb) {
            while ((n0i < 0 || n1i < 0) && ti < NT) {
                unsigned short w0 = *(const unsigned short*)(m8 + rb + (ti    ) * ND);
                unsigned short w1 = *(const unsigned short*)(m8 + rb + (ti + 1) * ND);
                unsigned short w2 = *(const unsigned short*)(m8 + rb + (ti + 2) * ND);
                unsigned short w3 = *(const unsigned short*)(m8 + rb + (ti + 3) * ND);
                if (n0i < 0) n0i = (w0 & 0xffu) ? ti : (w1 & 0xffu) ? ti+1 : (w2 & 0xffu) ? ti+2 : (w3 & 0xffu) ? ti+3 : -1;
                if (n1i < 0) n1i = (w0 >> 8) ? ti : (w1 >> 8) ? ti+1 : (w2 >> 8) ? ti+2 : (w3 >> 8) ? ti+3 : -1;
                ti += 4;
            }
        } else {
            while ((n0i < 0 || n1i < 0) && ti < NT) {
                int2 w0 = m32[rb2 + (ti    ) * (ND / 2)];
                int2 w1 = m32[rb2 + (ti + 1) * (ND / 2)];
                int2 w2 = m32[rb2 + (ti + 2) * (ND / 2)];
                int2 w3 = m32[rb2 + (ti + 3) * (ND / 2)];
                if (n0i < 0) n0i = w0.x ? ti : w1.x ? ti+1 : w2.x ? ti+2 : w3.x ? ti+3 : -1;
                if (n1i < 0) n1i = w0.y ? ti : w1.y ? ti+1 : w2.y ? ti+2 : w3.y ? ti+3 : -1;
                ti += 4;
            }
        }
    }
    float nx0 = 0.f, nx1 = 0.f, nt0, nt1;
    if (n0i >= 0) { nx0 = v[rb + n0i * ND];     nt0 = t[rb + n0i * ND];     } else nt0 = t[rb + (NT - 1) * ND];
    if (n1i >= 0) { nx1 = v[rb + 1 + n1i * ND]; nt1 = t[rb + 1 + n1i * ND]; } else nt1 = t[rb + 1 + (NT - 1) * ND];

    // ---- backward sweep: inclusive backward fill + interpolation ----
#pragma unroll
    for (int tt = CH - 1; tt >= 0; --tt) {
        float2 o;
        // lane 0
        {
            float xl = LX[tt].x, tl = LT[tt].x, tv = TV[tt].x;
            float den = nt0 - tl;
            float r = xl + (nx0 - xl) * __fdividef(tv - tl, den);
            bool ok = (den != 0.f) && isfinite(r);
            if ((bA >> tt) & 1u) {
                o.x = xl;                        // observed: forward fill == v
                nx0 = xl; nt0 = tv;
            } else {
                o.x = ok ? r : 0.f;
            }
        }
        // lane 1
        {
            float xl = LX[tt].y, tl = LT[tt].y, tv = TV[tt].y;
            float den = nt1 - tl;
            float r = xl + (nx1 - xl) * __fdividef(tv - tl, den);
            bool ok = (den != 0.f) && isfinite(r);
            if ((bB >> tt) & 1u) {
                o.y = xl;
                nx1 = xl; nt1 = tv;
            } else {
                o.y = ok ? r : 0.f;
            }
        }
        o2[base2 + tt * (ND / 2)] = o;
    }
}

// ---------------------------------------------------------------------------
extern "C" void kernel_launch(void* const* d_in, const int* in_sizes, int n_in,
                              void* d_out, int out_size) {
    const float* values = (const float*)d_in[0];
    const float* times  = (const float*)d_in[1];
    const void*  mask   = d_in[2];

    (void)n_in; (void)in_sizes; (void)out_size;

    // Single fused launch: streams mask (+small probe overage), v, t once;
    // writes out once.
    k_all<<<(NB * NC * (ND / 2)) / 128, 128>>>(values, times, mask, (float*)d_out);
}

// round 8
// speedup vs baseline: 1.1784x; 1.0096x over previous
#include <cuda_runtime.h>
#include <cstdint>
#include <math.h>

// Problem shape (fixed by the reference)
#define NB 32
#define NT 2048
#define ND 128
#define CH 8           // timesteps per thread-chunk
#define NC 256         // NT / CH

// ---------------------------------------------------------------------------
// Single fused kernel. Thread = (b, chunk c, lane pair d2=2*dg).
// Order matters for MLP:
//   1. issue all bulk v/t chunk loads (16 LDG.64, independent)
//   2. mask dtype detection + chunk mask bits (independent loads)
//   3. forward+backward seed probes INTERLEAVED (overlapping chains)
//   4. seed gathers, forward fill (consumes preloaded regs), backward interp
// ---------------------------------------------------------------------------
__global__ void __launch_bounds__(128) k_all(const float* __restrict__ v,
                                             const float* __restrict__ t,
                                             const void*  __restrict__ mraw,
                                             float* __restrict__ out) {
    const int gid = blockIdx.x * 128 + threadIdx.x;
    const int dg = gid & 63;                 // ND/2 = 64 lane pairs
    const int c  = (gid >> 6) & (NC - 1);
    const int b  = gid >> 14;                // 6 + log2(NC)
    const int d2 = dg * 2;

    const float2* v2 = (const float2*)v;
    const float2* t2 = (const float2*)t;
    float2* o2 = (float2*)out;

    const int rb  = b * NT * ND + d2;            // scalar row base (lane 0)
    const int rb2 = b * NT * (ND / 2) + dg;      // float2/int2 row base
    const int base2 = rb2 + (c * CH) * (ND / 2);
    const unsigned char* m8 = (const unsigned char*)mraw;
    const int2* m32 = (const int2*)mraw;

    // ---- 1. bulk payload loads first: 16 independent LDG.64 ----
    float2 VV[CH], TT[CH];
#pragma unroll
    for (int tt = 0; tt < CH; ++tt) {
        VV[tt] = v2[base2 + tt * (ND / 2)];
        TT[tt] = t2[base2 + tt * (ND / 2)];
    }

    // ---- 2. mask dtype detection (ballot over first 32 words) ----
    // int32 0/1 words are always <=1; packed bool bytes give a word >1 over
    // 32 words w.p. 1-(1/8)^32. Bool-as-int32 0/1 takes the int path: correct.
    __shared__ int s_isb;
    if (threadIdx.x < 32) {
        unsigned int w = ((const unsigned int*)mraw)[threadIdx.x];
        unsigned int any = __ballot_sync(0xffffffffu, w > 1u);
        if (threadIdx.x == 0) s_isb = (any != 0u);
    }
    __syncthreads();
    const bool isb = (s_isb != 0);

    // ---- chunk mask bits (tiny loads; warp-coalesced) ----
    unsigned int bA = 0, bB = 0;
    if (isb) {
#pragma unroll
        for (int tt = 0; tt < CH; ++tt) {
            unsigned short w = *(const unsigned short*)(m8 + rb + (c * CH + tt) * ND);
            bA |= ((w & 0xffu) ? 1u : 0u) << tt;
            bB |= ((w >> 8)    ? 1u : 0u) << tt;
        }
    } else {
#pragma unroll
        for (int tt = 0; tt < CH; ++tt) {
            int2 w = m32[base2 + tt * (ND / 2)];
            bA |= (w.x ? 1u : 0u) << tt;
            bB |= (w.y ? 1u : 0u) << tt;
        }
    }

    // ---- 3. interleaved seed probes (both directions in flight) ----
    // Regions [0, c*CH) and [(c+1)*CH, NT) have lengths multiple of 8,
    // so 4-step batches never cross the array bounds.
    int f0 = -1, f1 = -1, n0i = -1, n1i = -1;
    {
        int fti = c * CH - 1;                // forward probe cursor (descending)
        int bti = (c + 1) * CH;              // backward probe cursor (ascending)
        bool fgo = fti >= 0;
        bool bgo = bti < NT;
        while ((fgo && (f0 < 0 || f1 < 0)) || (bgo && (n0i < 0 || n1i < 0))) {
            if (fgo && (f0 < 0 || f1 < 0)) {
                unsigned int a0, a1, a2, a3, b0_, b1_, b2_, b3_;
                if (isb) {
                    unsigned short w0 = *(const unsigned short*)(m8 + rb + (fti    ) * ND);
                    unsigned short w1 = *(const unsigned short*)(m8 + rb + (fti - 1) * ND);
                    unsigned short w2 = *(const unsigned short*)(m8 + rb + (fti - 2) * ND);
                    unsigned short w3 = *(const unsigned short*)(m8 + rb + (fti - 3) * ND);
                    a0 = w0 & 0xffu; a1 = w1 & 0xffu; a2 = w2 & 0xffu; a3 = w3 & 0xffu;
                    b0_ = w0 >> 8;   b1_ = w1 >> 8;   b2_ = w2 >> 8;   b3_ = w3 >> 8;
                } else {
                    int2 w0 = m32[rb2 + (fti    ) * (ND / 2)];
                    int2 w1 = m32[rb2 + (fti - 1) * (ND / 2)];
                    int2 w2 = m32[rb2 + (fti - 2) * (ND / 2)];
                    int2 w3 = m32[rb2 + (fti - 3) * (ND / 2)];
                    a0 = w0.x; a1 = w1.x; a2 = w2.x; a3 = w3.x;
                    b0_ = w0.y; b1_ = w1.y; b2_ = w2.y; b3_ = w3.y;
                }
                if (f0 < 0) f0 = a0 ? fti : a1 ? fti-1 : a2 ? fti-2 : a3 ? fti-3 : -1;
                if (f1 < 0) f1 = b0_ ? fti : b1_ ? fti-1 : b2_ ? fti-2 : b3_ ? fti-3 : -1;
                fti -= 4;
                fgo = fti >= 0;
            }
            if (bgo && (n0i < 0 || n1i < 0)) {
                unsigned int a0, a1, a2, a3, b0_, b1_, b2_, b3_;
                if (isb) {
                    unsigned short w0 = *(const unsigned short*)(m8 + rb + (bti    ) * ND);
                    unsigned short w1 = *(const unsigned short*)(m8 + rb + (bti + 1) * ND);
                    unsigned short w2 = *(const unsigned short*)(m8 + rb + (bti + 2) * ND);
                    unsigned short w3 = *(const unsigned short*)(m8 + rb + (bti + 3) * ND);
                    a0 = w0 & 0xffu; a1 = w1 & 0xffu; a2 = w2 & 0xffu; a3 = w3 & 0xffu;
                    b0_ = w0 >> 8;   b1_ = w1 >> 8;   b2_ = w2 >> 8;   b3_ = w3 >> 8;
                } else {
                    int2 w0 = m32[rb2 + (bti    ) * (ND / 2)];
                    int2 w1 = m32[rb2 + (bti + 1) * (ND / 2)];
                    int2 w2 = m32[rb2 + (bti + 2) * (ND / 2)];
                    int2 w3 = m32[rb2 + (bti + 3) * (ND / 2)];
                    a0 = w0.x; a1 = w1.x; a2 = w2.x; a3 = w3.x;
                    b0_ = w0.y; b1_ = w1.y; b2_ = w2.y; b3_ = w3.y;
                }
                if (n0i < 0) n0i = a0 ? bti : a1 ? bti+1 : a2 ? bti+2 : a3 ? bti+3 : -1;
                if (n1i < 0) n1i = b0_ ? bti : b1_ ? bti+1 : b2_ ? bti+2 : b3_ ? bti+3 : -1;
                bti += 4;
                bgo = bti < NT;
            }
        }
    }

    // ---- 4. seed gathers (overlap with forward fill below) ----
    float lx0 = 0.f, lx1 = 0.f, lt0, lt1;
    if (f0 >= 0) { lx0 = v[rb + f0 * ND];     lt0 = t[rb + f0 * ND];     } else lt0 = t[rb];
    if (f1 >= 0) { lx1 = v[rb + 1 + f1 * ND]; lt1 = t[rb + 1 + f1 * ND]; } else lt1 = t[rb + 1];
    float nx0 = 0.f, nx1 = 0.f, nt0, nt1;
    if (n0i >= 0) { nx0 = v[rb + n0i * ND];     nt0 = t[rb + n0i * ND];     } else nt0 = t[rb + (NT - 1) * ND];
    if (n1i >= 0) { nx1 = v[rb + 1 + n1i * ND]; nt1 = t[rb + 1 + n1i * ND]; } else nt1 = t[rb + 1 + (NT - 1) * ND];

    // ---- forward sweep: inclusive forward fill (consumes VV/TT) ----
    float2 LX[CH], LT[CH];
#pragma unroll
    for (int tt = 0; tt < CH; ++tt) {
        if ((bA >> tt) & 1u) { lx0 = VV[tt].x; lt0 = TT[tt].x; }
        if ((bB >> tt) & 1u) { lx1 = VV[tt].y; lt1 = TT[tt].y; }
        LX[tt] = make_float2(lx0, lx1);
        LT[tt] = make_float2(lt0, lt1);
    }

    // ---- backward sweep: inclusive backward fill + interpolation ----
#pragma unroll
    for (int tt = CH - 1; tt >= 0; --tt) {
        float2 o;
        // lane 0
        {
            float xl = LX[tt].x, tl = LT[tt].x, tv = TT[tt].x;
            float den = nt0 - tl;
            float r = xl + (nx0 - xl) * __fdividef(tv - tl, den);
            bool ok = (den != 0.f) && isfinite(r);
            if ((bA >> tt) & 1u) {
                o.x = xl;                        // observed: forward fill == v
                nx0 = xl; nt0 = tv;
            } else {
                o.x = ok ? r : 0.f;
            }
        }
        // lane 1
        {
            float xl = LX[tt].y, tl = LT[tt].y, tv = TT[tt].y;
            float den = nt1 - tl;
            float r = xl + (nx1 - xl) * __fdividef(tv - tl, den);
            bool ok = (den != 0.f) && isfinite(r);
            if ((bB >> tt) & 1u) {
                o.y = xl;
                nx1 = xl; nt1 = tv;
            } else {
                o.y = ok ? r : 0.f;
            }
        }
        o2[base2 + tt * (ND / 2)] = o;
    }
}

// ---------------------------------------------------------------------------
extern "C" void kernel_launch(void* const* d_in, const int* in_sizes, int n_in,
                              void* d_out, int out_size) {
    const float* values = (const float*)d_in[0];
    const float* times  = (const float*)d_in[1];
    const void*  mask   = d_in[2];

    (void)n_in; (void)in_sizes; (void)out_size;

    // Single fused launch: streams mask (+small probe overage), v, t once;
    // writes out once.
    k_all<<<(NB * NC * (ND / 2)) / 128, 128>>>(values, times, mask, (float*)d_out);
}